// round 1
// baseline (speedup 1.0000x reference)
#include <cuda_runtime.h>
#include <cstdint>

#define NN 100000
#define DF 64

// Scratch (allocation-free rule: __device__ globals)
__device__ __align__(16) float g_sums[(size_t)NN * DF];
__device__ int g_deg[NN];

// ---------------------------------------------------------------------------
// Kernel 0: zero the scratch accumulators (graph replays require re-zeroing)
// ---------------------------------------------------------------------------
__global__ void zero_kernel() {
    int tid = blockIdx.x * blockDim.x + threadIdx.x;
    int stride = gridDim.x * blockDim.x;
    const int total4 = NN * DF / 4;
    float4 z = make_float4(0.f, 0.f, 0.f, 0.f);
    for (int t = tid; t < total4; t += stride)
        reinterpret_cast<float4*>(g_sums)[t] = z;
    for (int t = tid; t < NN; t += stride)
        g_deg[t] = 0;
}

// ---------------------------------------------------------------------------
// Kernel 1: edge scatter. Half-warp (16 lanes) per edge:
//   gather h[src] as 16 x float4 (coalesced 256B), scatter-add into g_sums[dst].
// ---------------------------------------------------------------------------
__global__ void scatter_kernel(const float* __restrict__ h,
                               const int* __restrict__ src,
                               const int* __restrict__ dst,
                               int E) {
    int gid = blockIdx.x * blockDim.x + threadIdx.x;
    int e = gid >> 4;
    int lane = gid & 15;
    if (e >= E) return;
    int s = __ldg(&src[e]);
    int d = __ldg(&dst[e]);
    float4 v = reinterpret_cast<const float4*>(h + (size_t)s * DF)[lane];
    float* o = g_sums + (size_t)d * DF + lane * 4;
    atomicAdd(o + 0, v.x);
    atomicAdd(o + 1, v.y);
    atomicAdd(o + 2, v.z);
    atomicAdd(o + 3, v.w);
    if (lane == 0) atomicAdd(&g_deg[d], 1);
}

// ---------------------------------------------------------------------------
// Kernel 2: out = relu(W @ (sum/deg) + b), 0 for deg==0 nodes.
// blockDim 256 = 64 output-columns (j) x 4 node slots.
// Each thread keeps W row j in 64 registers (loaded once per block);
// x is staged in smem and read as warp-broadcast (conflict-free).
// ---------------------------------------------------------------------------
__global__ void __launch_bounds__(256, 2)
out_kernel(const float* __restrict__ W, const float* __restrict__ b,
           float* __restrict__ out, int N) {
    __shared__ float xs[4][DF];
    const int j = threadIdx.x & 63;
    const int slot = threadIdx.x >> 6;

    float Wr[DF];
#pragma unroll
    for (int k = 0; k < DF; k++) Wr[k] = W[j * DF + k];
    const float bj = b[j];

    for (int n0 = blockIdx.x * 4; n0 < N; n0 += gridDim.x * 4) {
        const int node = n0 + slot;
        int dg = 0;
        if (node < N) {
            dg = g_deg[node];
            float inv = (dg > 0) ? (1.0f / (float)dg) : 0.0f;
            xs[slot][j] = g_sums[(size_t)node * DF + j] * inv;
        }
        __syncthreads();
        if (node < N) {
            float acc = bj;
#pragma unroll
            for (int k = 0; k < DF; k++)
                acc = fmaf(Wr[k], xs[slot][k], acc);
            out[(size_t)node * DF + j] = (dg > 0) ? fmaxf(acc, 0.0f) : 0.0f;
        }
        __syncthreads();
    }
}

// ---------------------------------------------------------------------------
extern "C" void kernel_launch(void* const* d_in, const int* in_sizes, int n_in,
                              void* d_out, int out_size) {
    const float* h   = (const float*)d_in[0];
    const int*   src = (const int*)d_in[1];
    const int*   dst = (const int*)d_in[2];
    const float* W   = (const float*)d_in[3];
    const float* b   = (const float*)d_in[4];
    float* out = (float*)d_out;

    const int N = in_sizes[0] / DF;   // 100000
    const int E = in_sizes[1];        // 1600000

    zero_kernel<<<592, 256>>>();

    long long scatter_threads = (long long)E * 16;
    int sblocks = (int)((scatter_threads + 255) / 256);
    scatter_kernel<<<sblocks, 256>>>(h, src, dst, E);

    out_kernel<<<1184, 256>>>(W, b, out, N);
}

// round 2
// speedup vs baseline: 1.5118x; 1.5118x over previous
#include <cuda_runtime.h>
#include <cstdint>

#define NN 100000
#define DF 64

// Scratch (allocation-free rule: __device__ globals)
__device__ __align__(16) float g_sums[(size_t)NN * DF];
__device__ int g_deg[NN];

// ---------------------------------------------------------------------------
// Kernel 0: zero the scratch accumulators (graph replays require re-zeroing)
// ---------------------------------------------------------------------------
__global__ void zero_kernel() {
    int tid = blockIdx.x * blockDim.x + threadIdx.x;
    int stride = gridDim.x * blockDim.x;
    const int total4 = NN * DF / 4;
    float4 z = make_float4(0.f, 0.f, 0.f, 0.f);
    for (int t = tid; t < total4; t += stride)
        reinterpret_cast<float4*>(g_sums)[t] = z;
    for (int t = tid; t < NN; t += stride)
        g_deg[t] = 0;
}

// ---------------------------------------------------------------------------
// Kernel 1: edge scatter. Half-warp (16 lanes) per edge:
//   gather h[src] as 16 x float4 (coalesced 256B), scatter-add into g_sums[dst]
//   with ONE red.global.add.v4.f32 per lane (4x fewer LTS atomic ops than
//   scalar atomicAdd).
// ---------------------------------------------------------------------------
__global__ void scatter_kernel(const float* __restrict__ h,
                               const int* __restrict__ src,
                               const int* __restrict__ dst,
                               int E) {
    int gid = blockIdx.x * blockDim.x + threadIdx.x;
    int e = gid >> 4;
    int lane = gid & 15;
    if (e >= E) return;
    int s = __ldg(&src[e]);
    int d = __ldg(&dst[e]);
    float4 v = reinterpret_cast<const float4*>(h + (size_t)s * DF)[lane];
    float* o = g_sums + (size_t)d * DF + lane * 4;
    asm volatile("red.global.add.v4.f32 [%0], {%1, %2, %3, %4};"
                 :: "l"(o), "f"(v.x), "f"(v.y), "f"(v.z), "f"(v.w)
                 : "memory");
    if (lane == 0) atomicAdd(&g_deg[d], 1);
}

// ---------------------------------------------------------------------------
// Kernel 2: out = relu(W @ (sum/deg) + b), 0 for deg==0 nodes.
// blockDim 256 = 64 output-columns (j) x 4 node slots.
// Each thread keeps W row j in 64 registers (loaded once per block);
// x is staged in smem and read as warp-broadcast (conflict-free).
// ---------------------------------------------------------------------------
__global__ void __launch_bounds__(256, 2)
out_kernel(const float* __restrict__ W, const float* __restrict__ b,
           float* __restrict__ out, int N) {
    __shared__ float xs[4][DF];
    const int j = threadIdx.x & 63;
    const int slot = threadIdx.x >> 6;

    float Wr[DF];
#pragma unroll
    for (int k = 0; k < DF; k++) Wr[k] = W[j * DF + k];
    const float bj = b[j];

    for (int n0 = blockIdx.x * 4; n0 < N; n0 += gridDim.x * 4) {
        const int node = n0 + slot;
        int dg = 0;
        if (node < N) {
            dg = g_deg[node];
            float inv = (dg > 0) ? (1.0f / (float)dg) : 0.0f;
            xs[slot][j] = g_sums[(size_t)node * DF + j] * inv;
        }
        __syncthreads();
        if (node < N) {
            float acc = bj;
#pragma unroll
            for (int k = 0; k < DF; k++)
                acc = fmaf(Wr[k], xs[slot][k], acc);
            out[(size_t)node * DF + j] = (dg > 0) ? fmaxf(acc, 0.0f) : 0.0f;
        }
        __syncthreads();
    }
}

// ---------------------------------------------------------------------------
extern "C" void kernel_launch(void* const* d_in, const int* in_sizes, int n_in,
                              void* d_out, int out_size) {
    const float* h   = (const float*)d_in[0];
    const int*   src = (const int*)d_in[1];
    const int*   dst = (const int*)d_in[2];
    const float* W   = (const float*)d_in[3];
    const float* b   = (const float*)d_in[4];
    float* out = (float*)d_out;

    const int N = in_sizes[0] / DF;   // 100000
    const int E = in_sizes[1];        // 1600000

    zero_kernel<<<592, 256>>>();

    long long scatter_threads = (long long)E * 16;
    int sblocks = (int)((scatter_threads + 255) / 256);
    scatter_kernel<<<sblocks, 256>>>(h, src, dst, E);

    out_kernel<<<1184, 256>>>(W, b, out, N);
}